// round 12
// baseline (speedup 1.0000x reference)
#include <cuda_runtime.h>
#include <cuda_bf16.h>
#include <cstdint>

#define NROWS 65536
#define DDIM  512
#define KCL   1024
#define MT    64
#define NTILE 256
#define NTILES 4                       // KCL / NTILE
#define KC    64
#define CHPT  8                        // k-chunks per N-tile
#define ASTRIDE 520                    // bf16 per A row (pad) -> 1040B

// smem byte offsets
#define AS_OFF 0
#define CS_OFF (MT * ASTRIDE * 2)            // 66560
#define XS_OFF (CS_OFF + KCL * 4)            // 70656
#define RS_OFF (XS_OFF + MT * 4)             // 70912
#define SMEM_TOTAL (RS_OFF + MT * 4)         // 71168

__device__ __align__(1024) __nv_bfloat16 g_cb[KCL * DDIM];  // clusters bf16 (L2-resident)
__device__ float g_csq[KCL];

static __device__ __forceinline__ uint32_t smaddr(const void* p) {
    return (uint32_t)__cvta_generic_to_shared(p);
}
static __device__ __forceinline__ void ldmatrix_x4(uint32_t r[4], uint32_t addr) {
    asm volatile("ldmatrix.sync.aligned.m8n8.x4.shared.b16 {%0,%1,%2,%3}, [%4];"
                 : "=r"(r[0]), "=r"(r[1]), "=r"(r[2]), "=r"(r[3]) : "r"(addr));
}
static __device__ __forceinline__ void mma_bf16(float c[4], const uint32_t a[4],
                                                uint32_t b0, uint32_t b1) {
    asm volatile(
        "mma.sync.aligned.m16n8k16.row.col.f32.bf16.bf16.f32 "
        "{%0,%1,%2,%3}, {%4,%5,%6,%7}, {%8,%9}, {%0,%1,%2,%3};"
        : "+f"(c[0]), "+f"(c[1]), "+f"(c[2]), "+f"(c[3])
        : "r"(a[0]), "r"(a[1]), "r"(a[2]), "r"(a[3]), "r"(b0), "r"(b1));
}

// ---------------- prep: clusters fp32 -> bf16, and ||c||^2 ----------------
__global__ void prep_clusters(const float* __restrict__ cl) {
    int row = blockIdx.x, t = threadIdx.x;
    float v = cl[row * DDIM + t];
    g_cb[row * DDIM + t] = __float2bfloat16_rn(v);
    float s = v * v;
    #pragma unroll
    for (int o = 16; o > 0; o >>= 1) s += __shfl_down_sync(0xffffffffu, s, o);
    __shared__ float ws[16];
    if ((t & 31) == 0) ws[t >> 5] = s;
    __syncthreads();
    if (t < 16) {
        float x2 = ws[t];
        #pragma unroll
        for (int o = 8; o > 0; o >>= 1) x2 += __shfl_down_sync(0xffffu, x2, o);
        if (t == 0) g_csq[row] = x2;
    }
}

// ------ main fused HMMA kernel: 256 thr, 8 warps, B direct from L2, no mainloop barriers ------
__global__ void __launch_bounds__(256, 2)
cluster_main(const float* __restrict__ x, float* __restrict__ out) {
    extern __shared__ __align__(1024) char sm[];
    const uint32_t sb = smaddr(sm);
    __nv_bfloat16* As = (__nv_bfloat16*)(sm + AS_OFF);
    float* cs = (float*)(sm + CS_OFF);
    float* xs = (float*)(sm + XS_OFF);
    float* rs = (float*)(sm + RS_OFF);

    const int tid  = threadIdx.x;
    const int lane = tid & 31;
    const int warp = tid >> 5;
    const int wn   = warp * 32;            // warp grid 1(M) x 8(N), tile 64x32
    const int m0   = blockIdx.x * MT;

    if (tid < MT) rs[tid] = 0.f;
    for (int i = tid; i < KCL; i += 256) cs[i] = g_csq[i];

    // A tile: 64 x 512 fp32 -> bf16 smem; per-row ||x||^2
    {
        const int row = tid >> 2, q = tid & 3;
        const float4* src = (const float4*)(x + (size_t)(m0 + row) * DDIM + q * 128);
        float s = 0.f;
        #pragma unroll 4
        for (int i = 0; i < 32; i++) {
            float4 v = src[i];
            s += v.x * v.x + v.y * v.y + v.z * v.z + v.w * v.w;
            __nv_bfloat162 p0 = __floats2bfloat162_rn(v.x, v.y);
            __nv_bfloat162 p1 = __floats2bfloat162_rn(v.z, v.w);
            uint2 pk; pk.x = *(uint32_t*)&p0; pk.y = *(uint32_t*)&p1;
            *(uint2*)&As[row * ASTRIDE + q * 128 + i * 4] = pk;
        }
        s += __shfl_xor_sync(0xffffffffu, s, 1);
        s += __shfl_xor_sync(0xffffffffu, s, 2);
        if ((lane & 3) == 0) xs[row] = s;
    }
    __syncthreads();   // A, xs, rs, cs ready; A is read-only from here on

    // A ldmatrix invariant address parts (rows mi*16 + lane-part, col halves)
    uint32_t a_base[4];
    #pragma unroll
    for (int mi = 0; mi < 4; mi++)
        a_base[mi] = sb + AS_OFF +
            (uint32_t)((mi * 16 + (lane & 7) + ((lane >> 3) & 1) * 8) * ASTRIDE) * 2 +
            (uint32_t)(lane >> 4) * 16;

    // B fragment lane base (PTX mma.m16n8k16 row.col B layout):
    // lane l covers n = base + (l>>2), k = kk + (l&3)*2 (+8 for the second reg)
    const int bl_n = lane >> 2;
    const int bl_k = (lane & 3) * 2;

    float acc[4][4][4];

    for (int nt = 0; nt < NTILES; nt++) {
        #pragma unroll
        for (int mi = 0; mi < 4; mi++)
            #pragma unroll
            for (int ni = 0; ni < 4; ni++)
                #pragma unroll
                for (int r = 0; r < 4; r++) acc[mi][ni][r] = 0.f;

        const uint32_t* bp = (const uint32_t*)
            (g_cb + (size_t)(nt * NTILE + wn + bl_n) * DDIM + bl_k);
        // element offsets below are in uint32 units (2 bf16 each)

        for (int kc = 0; kc < CHPT; kc++) {
            #pragma unroll
            for (int ks = 0; ks < 4; ks++) {
                const int kk = kc * KC + ks * 16;
                // B: 8 LDG.32 straight from L2
                uint32_t b[4][2];
                #pragma unroll
                for (int g = 0; g < 4; g++) {
                    const uint32_t* p = bp + (size_t)(g * 8) * (DDIM / 2) + kk / 2;
                    b[g][0] = __ldg(p);
                    b[g][1] = __ldg(p + 4);
                }
                // A: 4 ldmatrix.x4 from smem
                uint32_t a[4][4];
                #pragma unroll
                for (int mi = 0; mi < 4; mi++)
                    ldmatrix_x4(a[mi], a_base[mi] + kk * 2);
                #pragma unroll
                for (int mi = 0; mi < 4; mi++)
                    #pragma unroll
                    for (int ni = 0; ni < 4; ni++)
                        mma_bf16(acc[mi][ni], a[mi], b[ni][0], b[ni][1]);
            }
        }

        // epilogue for N-tile nt: q = 1/(1+dist2), store, row-sums
        const int n0 = nt * NTILE + wn;
        #pragma unroll
        for (int mi = 0; mi < 4; mi++) {
            const int rlo = mi * 16 + (lane >> 2);
            const int rhi = rlo + 8;
            const float xlo = xs[rlo], xhi = xs[rhi];
            float rs0 = 0.f, rs1 = 0.f;
            #pragma unroll
            for (int ni = 0; ni < 4; ni++) {
                const int c = n0 + ni * 8 + (lane & 3) * 2;
                const float2 cc = *(const float2*)&cs[c];
                float q00 = __fdividef(1.f, 1.f + fmaxf(xlo + cc.x - 2.f * acc[mi][ni][0], 0.f));
                float q01 = __fdividef(1.f, 1.f + fmaxf(xlo + cc.y - 2.f * acc[mi][ni][1], 0.f));
                float q10 = __fdividef(1.f, 1.f + fmaxf(xhi + cc.x - 2.f * acc[mi][ni][2], 0.f));
                float q11 = __fdividef(1.f, 1.f + fmaxf(xhi + cc.y - 2.f * acc[mi][ni][3], 0.f));
                *(float2*)&out[(size_t)(m0 + rlo) * KCL + c] = make_float2(q00, q01);
                *(float2*)&out[(size_t)(m0 + rhi) * KCL + c] = make_float2(q10, q11);
                rs0 += q00 + q01;
                rs1 += q10 + q11;
            }
            rs0 += __shfl_xor_sync(0xffffffffu, rs0, 1);
            rs0 += __shfl_xor_sync(0xffffffffu, rs0, 2);
            rs1 += __shfl_xor_sync(0xffffffffu, rs1, 1);
            rs1 += __shfl_xor_sync(0xffffffffu, rs1, 2);
            if ((lane & 3) == 0) {
                atomicAdd(&rs[rlo], rs0);
                atomicAdd(&rs[rhi], rs1);
            }
        }
    }
    __syncthreads();   // all stores + row-sum atomics done

    // normalize pass: CTA's own 256KB out region (L2-hot)
    {
        const int row = tid >> 2, q = tid & 3;
        const float inv = __fdividef(1.f, rs[row]);
        float4* p = (float4*)(out + (size_t)(m0 + row) * KCL + q * 256);
        #pragma unroll 4
        for (int i = 0; i < 64; i++) {
            float4 v = p[i];
            v.x *= inv; v.y *= inv; v.z *= inv; v.w *= inv;
            p[i] = v;
        }
    }
}

extern "C" void kernel_launch(void* const* d_in, const int* in_sizes, int n_in,
                              void* d_out, int out_size) {
    const float* x        = (const float*)d_in[0];
    const float* clusters = (const float*)d_in[1];
    float* out = (float*)d_out;

    cudaFuncSetAttribute(cluster_main,
                         cudaFuncAttributeMaxDynamicSharedMemorySize, SMEM_TOTAL);

    prep_clusters<<<KCL, DDIM>>>(clusters);
    cluster_main<<<NROWS / MT, 256, SMEM_TOTAL>>>(x, out);
}

// round 14
// speedup vs baseline: 1.3529x; 1.3529x over previous
#include <cuda_runtime.h>
#include <cuda_bf16.h>
#include <cstdint>

#define NROWS 65536
#define DDIM  512
#define KCL   1024
#define MT    128
#define GTILE 64                       // N cols per tile (per group)
#define KC    64
#define CHPT  8                        // k-chunks per tile
#define TPG   4                        // tiles per group
#define TOTCH (TPG * CHPT)             // 32 chunks per group
#define ASTRIDE 520                    // bf16 per A row (pad) -> 1040B
#define BROWB 144                      // bytes per B row (64 bf16 + 16B pad)
#define STAGEB (GTILE * BROWB)         // 9216
// 8 stages total: group g owns slots {2g, 2g+1}

// smem byte offsets
#define AS_OFF 0
#define BS_OFF (MT * ASTRIDE * 2)            // 133120
#define CS_OFF (BS_OFF + 8 * STAGEB)         // 206848
#define XS_OFF (CS_OFF + KCL * 4)            // 210944
#define RS_OFF (XS_OFF + MT * 4)             // 211456
#define SMEM_TOTAL (RS_OFF + MT * 4)         // 211968

__device__ __align__(1024) __nv_bfloat16 g_cb[KCL * DDIM];  // clusters bf16
__device__ float g_csq[KCL];

static __device__ __forceinline__ uint32_t smaddr(const void* p) {
    return (uint32_t)__cvta_generic_to_shared(p);
}
static __device__ __forceinline__ void ldmatrix_x4(uint32_t r[4], uint32_t addr) {
    asm volatile("ldmatrix.sync.aligned.m8n8.x4.shared.b16 {%0,%1,%2,%3}, [%4];"
                 : "=r"(r[0]), "=r"(r[1]), "=r"(r[2]), "=r"(r[3]) : "r"(addr));
}
static __device__ __forceinline__ void mma_bf16(float c[4], const uint32_t a[4],
                                                uint32_t b0, uint32_t b1) {
    asm volatile(
        "mma.sync.aligned.m16n8k16.row.col.f32.bf16.bf16.f32 "
        "{%0,%1,%2,%3}, {%4,%5,%6,%7}, {%8,%9}, {%0,%1,%2,%3};"
        : "+f"(c[0]), "+f"(c[1]), "+f"(c[2]), "+f"(c[3])
        : "r"(a[0]), "r"(a[1]), "r"(a[2]), "r"(a[3]), "r"(b0), "r"(b1));
}
static __device__ __forceinline__ void bar_grp(int grp) {
    asm volatile("bar.sync %0, 128;" :: "r"(grp + 1) : "memory");
}

// ---------------- prep: clusters fp32 -> bf16, and ||c||^2 ----------------
__global__ void prep_clusters(const float* __restrict__ cl) {
    int row = blockIdx.x, t = threadIdx.x;
    float v = cl[row * DDIM + t];
    g_cb[row * DDIM + t] = __float2bfloat16_rn(v);
    float s = v * v;
    #pragma unroll
    for (int o = 16; o > 0; o >>= 1) s += __shfl_down_sync(0xffffffffu, s, o);
    __shared__ float ws[16];
    if ((t & 31) == 0) ws[t >> 5] = s;
    __syncthreads();
    if (t < 16) {
        float x2 = ws[t];
        #pragma unroll
        for (int o = 8; o > 0; o >>= 1) x2 += __shfl_down_sync(0xffffu, x2, o);
        if (t == 0) g_csq[row] = x2;
    }
}

// ------- main fused HMMA kernel: 512 thr, four independent 4-warp pipelines -------
__global__ void __launch_bounds__(512, 1)
cluster_main(const float* __restrict__ x, float* __restrict__ out) {
    extern __shared__ __align__(1024) char sm[];
    const uint32_t sb = smaddr(sm);
    __nv_bfloat16* As = (__nv_bfloat16*)(sm + AS_OFF);
    float* cs = (float*)(sm + CS_OFF);
    float* xs = (float*)(sm + XS_OFF);
    float* rs = (float*)(sm + RS_OFF);

    const int tid  = threadIdx.x;
    const int lane = tid & 31;
    const int warp = tid >> 5;
    const int grp  = warp >> 2;            // pipeline group 0..3
    const int gw   = warp & 3;             // warp within group
    const int gtid = tid & 127;
    const int wm = (gw & 1) * 64;          // group warp grid 2(M) x 2(N), tile 64x32
    const int wn = (gw >> 1) * 32;
    const int ncol0 = grp * (TPG * GTILE); // this group's N-column base
    const int m0 = blockIdx.x * MT;

    if (tid < MT) rs[tid] = 0.f;
    for (int i = tid; i < KCL; i += 512) cs[i] = g_csq[i];

    // cp.async one B stage (group chunk c): 64 rows x 64 bf16 = 512 x 16B,
    // executed by this group's 128 threads (4 transfers each)
    auto cp_stage = [&](int c) {
        const int tile = c >> 3, kc = c & 7;
        const __nv_bfloat16* src0 =
            g_cb + (size_t)(ncol0 + tile * GTILE) * DDIM + kc * KC;
        const uint32_t dbase = sb + BS_OFF + (uint32_t)(grp * 2 + (c & 1)) * STAGEB;
        #pragma unroll
        for (int j = 0; j < 4; j++) {
            int g = j * 128 + gtid;          // [0, 512)
            int row = g >> 3, cc = g & 7;
            const __nv_bfloat16* gp = src0 + (size_t)row * DDIM + cc * 8;
            asm volatile("cp.async.cg.shared.global [%0], [%1], 16;"
                         :: "r"(dbase + row * BROWB + cc * 16), "l"(gp));
        }
        asm volatile("cp.async.commit_group;");
    };

    cp_stage(0);   // each group prefetches its first stage

    // A tile: 128 x 512 fp32 -> bf16 smem; per-row ||x||^2 (whole CTA)
    {
        const int row = tid >> 2, q = tid & 3;
        const float4* src = (const float4*)(x + (size_t)(m0 + row) * DDIM + q * 128);
        float s = 0.f;
        #pragma unroll 4
        for (int i = 0; i < 32; i++) {
            float4 v = src[i];
            s += v.x * v.x + v.y * v.y + v.z * v.z + v.w * v.w;
            __nv_bfloat162 p0 = __floats2bfloat162_rn(v.x, v.y);
            __nv_bfloat162 p1 = __floats2bfloat162_rn(v.z, v.w);
            uint2 pk; pk.x = *(uint32_t*)&p0; pk.y = *(uint32_t*)&p1;
            *(uint2*)&As[row * ASTRIDE + q * 128 + i * 4] = pk;
        }
        s += __shfl_xor_sync(0xffffffffu, s, 1);
        s += __shfl_xor_sync(0xffffffffu, s, 2);
        if ((lane & 3) == 0) xs[row] = s;
    }
    __syncthreads();   // A + xs + rs + cs visible to everyone

    // per-thread invariant ldmatrix address parts
    uint32_t a_base[4], b_lane;
    #pragma unroll
    for (int mi = 0; mi < 4; mi++)
        a_base[mi] = sb + AS_OFF +
            (uint32_t)((wm + mi * 16 + (lane & 7) + ((lane >> 3) & 1) * 8) * ASTRIDE) * 2 +
            (uint32_t)(lane >> 4) * 16;
    b_lane = (uint32_t)((lane >> 4) * 8 + (lane & 7)) * BROWB + ((lane >> 3) & 1) * 16;

    float acc[4][4][4];   // 4 mi x 2 ni-pairs... kept 4x4 layout: ni over 32 cols

    for (int t = 0; t < TOTCH; t++) {
        const int kc = t & 7, tile = t >> 3;
        if (kc == 0) {
            #pragma unroll
            for (int mi = 0; mi < 4; mi++)
                #pragma unroll
                for (int ni = 0; ni < 4; ni++)
                    #pragma unroll
                    for (int r = 0; r < 4; r++) acc[mi][ni][r] = 0.f;
        }

        asm volatile("cp.async.wait_group 0;");   // this group's stage t landed
        bar_grp(grp);                             // group's readers of other slot done
        if (t + 1 < TOTCH) cp_stage(t + 1);       // fill other slot under compute

        const uint32_t bst = sb + BS_OFF + (uint32_t)(grp * 2 + (t & 1)) * STAGEB + b_lane;
        const uint32_t b0 = bst + (uint32_t)(wn)      * BROWB;
        const uint32_t b1 = bst + (uint32_t)(wn + 16) * BROWB;

        #pragma unroll
        for (int ks = 0; ks < 4; ks++) {
            const int kk = kc * KC + ks * 16;
            uint32_t a[4][4], b[2][4];
            #pragma unroll
            for (int mi = 0; mi < 4; mi++)
                ldmatrix_x4(a[mi], a_base[mi] + kk * 2);
            ldmatrix_x4(b[0], b0 + ks * 32);
            ldmatrix_x4(b[1], b1 + ks * 32);
            #pragma unroll
            for (int mi = 0; mi < 4; mi++)
                #pragma unroll
                for (int ni = 0; ni < 4; ni++)
                    mma_bf16(acc[mi][ni], a[mi],
                             b[ni >> 1][(ni & 1) * 2],
                             b[ni >> 1][(ni & 1) * 2 + 1]);
        }

        if (kc == 7) {
            // epilogue for this group's tile: q = 1/(1+dist2), store, row-sums
            const int n0 = ncol0 + tile * GTILE + wn;
            #pragma unroll
            for (int mi = 0; mi < 4; mi++) {
                const int rlo = wm + mi * 16 + (lane >> 2);
                const int rhi = rlo + 8;
                const float xlo = xs[rlo], xhi = xs[rhi];
                float rs0 = 0.f, rs1 = 0.f;
                #pragma unroll
                for (int ni = 0; ni < 4; ni++) {
                    const int c = n0 + ni * 8 + (lane & 3) * 2;
                    const float2 cc = *(const float2*)&cs[c];
                    float q00 = __fdividef(1.f, 1.f + fmaxf(xlo + cc.x - 2.f * acc[mi][ni][0], 0.f));
                    float q01 = __fdividef(1.f, 1.f + fmaxf(xlo + cc.y - 2.f * acc[mi][ni][1], 0.f));
                    float q10 = __fdividef(1.f, 1.f + fmaxf(xhi + cc.x - 2.f * acc[mi][ni][2], 0.f));
                    float q11 = __fdividef(1.f, 1.f + fmaxf(xhi + cc.y - 2.f * acc[mi][ni][3], 0.f));
                    *(float2*)&out[(size_t)(m0 + rlo) * KCL + c] = make_float2(q00, q01);
                    *(float2*)&out[(size_t)(m0 + rhi) * KCL + c] = make_float2(q10, q11);
                    rs0 += q00 + q01;
                    rs1 += q10 + q11;
                }
                rs0 += __shfl_xor_sync(0xffffffffu, rs0, 1);
                rs0 += __shfl_xor_sync(0xffffffffu, rs0, 2);
                rs1 += __shfl_xor_sync(0xffffffffu, rs1, 1);
                rs1 += __shfl_xor_sync(0xffffffffu, rs1, 2);
                if ((lane & 3) == 0) {
                    atomicAdd(&rs[rlo], rs0);
                    atomicAdd(&rs[rhi], rs1);
                }
            }
        }
    }
    __syncthreads();   // all groups' row-sum contributions + stores done

    // normalize pass: CTA's own 512KB out region (L2-hot)
    {
        const int row = tid >> 2, q = tid & 3;
        const float inv = __fdividef(1.f, rs[row]);
        float4* p = (float4*)(out + (size_t)(m0 + row) * KCL + q * 256);
        #pragma unroll 4
        for (int i = 0; i < 64; i++) {
            float4 v = p[i];
            v.x *= inv; v.y *= inv; v.z *= inv; v.w *= inv;
            p[i] = v;
        }
    }
}

extern "C" void kernel_launch(void* const* d_in, const int* in_sizes, int n_in,
                              void* d_out, int out_size) {
    const float* x        = (const float*)d_in[0];
    const float* clusters = (const float*)d_in[1];
    float* out = (float*)d_out;

    cudaFuncSetAttribute(cluster_main,
                         cudaFuncAttributeMaxDynamicSharedMemorySize, SMEM_TOTAL);

    prep_clusters<<<KCL, DDIM>>>(clusters);
    cluster_main<<<NROWS / MT, 512, SMEM_TOTAL>>>(x, out);
}